// round 11
// baseline (speedup 1.0000x reference)
#include <cuda_runtime.h>
#include <cstdint>

// GatedBlockParity: N x 2048 fp32 in -> N x 1664 fp32 out
// in row:  [0,256) scalars | [256,640) gates (384) | [640,1408) ns1 (256x3) | [1408,2048) ns2 (128x5)
// out row: [0,256) relu(scalars) | [256,1024) ns1*sig(g1) | [1024,1664) ns2*sig(g2)

static constexpr int IN_W   = 2048;
static constexpr int OUT_W  = 1664;
static constexpr int OUT_W4 = OUT_W / 4;   // 416 float4 per row -> tid == c4

__device__ __forceinline__ float sigmoidf_(float x) {
    return 1.0f / (1.0f + __expf(-x));
}

// Persistent fixed-column kernel: tid==c4 forever; block grid-strides over
// row-pairs (r, r+rowsHalf). Region/i0/r/predicates computed ONCE.
// Software pipeline with distance-1 prefetch: next iteration's 2 data
// LDG.128s + 4 gate LDGs are issued before the current iteration's
// sigmoid/multiply/store, keeping the load stream continuously fed.
__global__ __launch_bounds__(416) void gbp_kernel(const float* __restrict__ in,
                                                  float* __restrict__ out,
                                                  int rowsHalf, int stride) {
    const int tid = threadIdx.x;
    const int c   = tid << 2;

    // ---- per-thread invariants -------------------------------------------
    int off, goff, r3;
    bool py, pz, pw;           // lane-selects: does lane use gate i0+1 ?
    bool isScalar = (c < 256); // warps 0,1
    if (isScalar) {
        off = c; goff = 256; r3 = 0; py = pz = pw = false;
    } else if (c < 1024) {
        int j  = c - 256;
        int i0 = j / 3;
        r3     = j - 3 * i0;
        off    = 640 + j;
        goff   = 256 + i0;
        py = (r3 == 2); pz = (r3 >= 1); pw = true;
    } else {
        int j  = c - 1024;
        int i0 = j / 5;
        r3     = j - 5 * i0;
        off    = 1408 + j;
        goff   = 512 + i0;            // goff+1 at i0=127 reads ns1[0]: valid, unused (r<2)
        py = (r3 == 4); pz = (r3 >= 3); pw = (r3 >= 2);
    }

    const size_t rowStepIn  = (size_t)stride * IN_W;    // row advance per iteration
    const size_t rowStepOut = (size_t)stride * OUT_W;
    const size_t halfIn     = (size_t)rowsHalf * IN_W;
    const size_t halfOut    = (size_t)rowsHalf * OUT_W;

    int row = blockIdx.x;
    if (row >= rowsHalf) return;

    const float* pA = in  + (size_t)row * IN_W;
    float*       pO = out + (size_t)row * OUT_W + c;

    // ---- prologue: load iteration 0 --------------------------------------
    float4 a = *reinterpret_cast<const float4*>(pA + off);
    float4 b = *reinterpret_cast<const float4*>(pA + halfIn + off);
    float ga0 = pA[goff],          ga1 = pA[goff + 1];
    float gb0 = pA[halfIn + goff], gb1 = pA[halfIn + goff + 1];

    for (;;) {
        int rn = row + stride;
        bool more = rn < rowsHalf;

        // ---- prefetch iteration i+1 (before any use of iteration i) ------
        float4 a2, b2;
        float na0 = 0.f, na1 = 0.f, nb0 = 0.f, nb1 = 0.f;
        const float* pN = pA + rowStepIn;
        if (more) {
            a2  = *reinterpret_cast<const float4*>(pN + off);
            b2  = *reinterpret_cast<const float4*>(pN + halfIn + off);
            na0 = pN[goff];          na1 = pN[goff + 1];
            nb0 = pN[halfIn + goff]; nb1 = pN[halfIn + goff + 1];
        }

        // ---- compute + store iteration i ---------------------------------
        if (isScalar) {
            a.x = fmaxf(a.x, 0.0f); a.y = fmaxf(a.y, 0.0f);
            a.z = fmaxf(a.z, 0.0f); a.w = fmaxf(a.w, 0.0f);
            b.x = fmaxf(b.x, 0.0f); b.y = fmaxf(b.y, 0.0f);
            b.z = fmaxf(b.z, 0.0f); b.w = fmaxf(b.w, 0.0f);
        } else {
            float sa0 = sigmoidf_(ga0), sa1 = sigmoidf_(ga1);
            float sb0 = sigmoidf_(gb0), sb1 = sigmoidf_(gb1);
            a.x *= sa0;                b.x *= sb0;
            a.y *= py ? sa1 : sa0;     b.y *= py ? sb1 : sb0;
            a.z *= pz ? sa1 : sa0;     b.z *= pz ? sb1 : sb0;
            a.w *= pw ? sa1 : sa0;     b.w *= pw ? sb1 : sb0;
        }
        *reinterpret_cast<float4*>(pO)           = a;
        *reinterpret_cast<float4*>(pO + halfOut) = b;

        if (!more) break;

        // ---- rotate pipeline ---------------------------------------------
        row = rn;
        pA  = pN;
        pO += rowStepOut;
        a = a2; b = b2;
        ga0 = na0; ga1 = na1; gb0 = nb0; gb1 = nb1;
    }
}

extern "C" void kernel_launch(void* const* d_in, const int* in_sizes, int n_in,
                              void* d_out, int out_size) {
    const float* in = (const float*)d_in[0];
    float* out = (float*)d_out;

    int n_rows   = in_sizes[0] / IN_W;      // 65536 (even)
    int rowsHalf = n_rows / 2;

    // Persistent grid: ~3 CTAs/SM on 148 SMs.
    int blocks = 444;
    if (blocks > rowsHalf) blocks = rowsHalf;

    gbp_kernel<<<blocks, OUT_W4>>>(in, out, rowsHalf, blocks);
}

// round 16
// speedup vs baseline: 1.1573x; 1.1573x over previous
#include <cuda_runtime.h>
#include <cstdint>

// GatedBlockParity: N x 2048 fp32 in -> N x 1664 fp32 out
// in row:  [0,256) scalars | [256,640) gates (384) | [640,1408) ns1 (256x3) | [1408,2048) ns2 (128x5)
// out row: [0,256) relu(scalars) | [256,1024) ns1*sig(g1) | [1024,1664) ns2*sig(g2)

static constexpr int IN_W   = 2048;
static constexpr int OUT_W  = 1664;
static constexpr int OUT_W4 = OUT_W / 4;   // 416 float4 per row -> one thread each

__device__ __forceinline__ float sigmoidf_(float x) {
    return 1.0f / (1.0f + __expf(-x));
}

// One 416-thread block per ADJACENT row pair (2b, 2b+1): the block's reads
// form one contiguous 16KB span and its writes one contiguous 13KB span
// (DRAM row-buffer / L2-sector friendly). threadIdx.x == c4 directly; the
// region boundaries (c4=64, c4=256) are warp-aligned -> zero divergence.
// Gate phase: coalesced float4 fill with sigmoid FUSED into the fill
// (LDG -> sigmoid -> STS), single barrier; consumers do one LDS each.
__global__ __launch_bounds__(416) void gbp_kernel(const float* __restrict__ in,
                                                  float* __restrict__ out) {
    // [0,384): sigmoid(gates row A); [384,768): row B; +8 pad for the
    // provably-unused i0+1 overread at the last ns2 group.
    __shared__ float sg[776];

    int tid = threadIdx.x;
    int c   = tid << 2;

    const float* __restrict__ iA = in + (size_t)blockIdx.x * (2 * IN_W);
    const float* __restrict__ iB = iA + IN_W;
    float* __restrict__ oA = out + (size_t)blockIdx.x * (2 * OUT_W) + c;
    float* __restrict__ oB = oA + OUT_W;

    // Region-dependent input offset (warp-uniform branch).
    int off;
    if (c < 256)       off = c;                   // scalars
    else if (c < 1024) off = 640  + (c - 256);    // ns1 data
    else               off = 1408 + (c - 1024);   // ns2 data

    // Issue the streaming data loads first; their latency overlaps the
    // whole gate phase below.
    float4 a = *reinterpret_cast<const float4*>(iA + off);
    float4 b = *reinterpret_cast<const float4*>(iB + off);

    // Fused gate fill + sigmoid: 2 rows x 96 float4 = 192 threads,
    // each LDG.128 -> 4 sigmoids -> STS.128. One barrier total.
    if (tid < 192) {
        bool rB = tid >= 96;
        int  t  = rB ? tid - 96 : tid;
        const float* gp = (rB ? iB : iA) + 256 + (t << 2);
        float4 g = *reinterpret_cast<const float4*>(gp);
        g.x = sigmoidf_(g.x);
        g.y = sigmoidf_(g.y);
        g.z = sigmoidf_(g.z);
        g.w = sigmoidf_(g.w);
        *reinterpret_cast<float4*>(&sg[(rB ? 384 : 0) + (t << 2)]) = g;
    }
    __syncthreads();

    if (c < 256) {
        // scalars: relu
        a.x = fmaxf(a.x, 0.0f); a.y = fmaxf(a.y, 0.0f);
        a.z = fmaxf(a.z, 0.0f); a.w = fmaxf(a.w, 0.0f);
        b.x = fmaxf(b.x, 0.0f); b.y = fmaxf(b.y, 0.0f);
        b.z = fmaxf(b.z, 0.0f); b.w = fmaxf(b.w, 0.0f);
    } else if (c < 1024) {
        // ns1: 256 groups of 3; gate i0=j/3, i0+1 (<=2 distinct per float4)
        int j  = c - 256;
        int i0 = j / 3;
        int r  = j - 3 * i0;
        float sa0 = sg[i0],       sa1 = sg[i0 + 1];
        float sb0 = sg[384 + i0], sb1 = sg[384 + i0 + 1];
        // lane gate idx: x->i0; y->i0+(r==2); z->i0+(r>=1); w->i0+1
        a.x *= sa0;                      b.x *= sb0;
        a.y *= (r == 2) ? sa1 : sa0;     b.y *= (r == 2) ? sb1 : sb0;
        a.z *= (r >= 1) ? sa1 : sa0;     b.z *= (r >= 1) ? sb1 : sb0;
        a.w *= sa1;                      b.w *= sb1;
    } else {
        // ns2: 128 groups of 5; gates live at sg[256+i] (A), sg[640+i] (B)
        int j  = c - 1024;
        int i0 = j / 5;
        int r  = j - 5 * i0;
        float sa0 = sg[256 + i0], sa1 = sg[256 + i0 + 1]; // i0=127 -> sg[384], unused (r<2)
        float sb0 = sg[640 + i0], sb1 = sg[640 + i0 + 1]; // i0=127 -> sg[768] pad, unused
        // lane gate idx: x->i0; y->i0+(r==4); z->i0+(r>=3); w->i0+(r>=2)
        a.x *= sa0;                      b.x *= sb0;
        a.y *= (r == 4) ? sa1 : sa0;     b.y *= (r == 4) ? sb1 : sb0;
        a.z *= (r >= 3) ? sa1 : sa0;     b.z *= (r >= 3) ? sb1 : sb0;
        a.w *= (r >= 2) ? sa1 : sa0;     b.w *= (r >= 2) ? sb1 : sb0;
    }

    *reinterpret_cast<float4*>(oA) = a;
    *reinterpret_cast<float4*>(oB) = b;
}

extern "C" void kernel_launch(void* const* d_in, const int* in_sizes, int n_in,
                              void* d_out, int out_size) {
    const float* in = (const float*)d_in[0];
    float* out = (float*)d_out;

    int n_rows = in_sizes[0] / IN_W;      // 65536 (even)
    int pairs  = n_rows / 2;

    gbp_kernel<<<pairs, OUT_W4>>>(in, out);
}

// round 17
// speedup vs baseline: 1.1741x; 1.0145x over previous
#include <cuda_runtime.h>
#include <cstdint>

// GatedBlockParity: N x 2048 fp32 in -> N x 1664 fp32 out
// in row:  [0,256) scalars | [256,640) gates (384) | [640,1408) ns1 (256x3) | [1408,2048) ns2 (128x5)
// out row: [0,256) relu(scalars) | [256,1024) ns1*sig(g1) | [1024,1664) ns2*sig(g2)

static constexpr int IN_W   = 2048;
static constexpr int OUT_W  = 1664;
static constexpr int OUT_W4 = OUT_W / 4;   // 416 float4 per row -> one thread each

__device__ __forceinline__ float sigmoidf_(float x) {
    return 1.0f / (1.0f + __expf(-x));
}

// One 416-thread block per SPLIT-HALF row pair (r, r+rowsHalf): the two
// streams sit 256MB apart, which the L2 addr hash spreads across slices/dies
// (measured better than adjacent pairing). threadIdx.x == c4 directly; the
// region boundaries (c4=64, c4=256) are warp-aligned -> zero divergence.
// Gate phase: coalesced float4 fill with sigmoid FUSED into the fill
// (LDG.128 -> 4x sigmoid -> STS.128), single barrier; consumers do one LDS.
__global__ __launch_bounds__(416) void gbp_kernel(const float* __restrict__ in,
                                                  float* __restrict__ out,
                                                  int rowsHalf) {
    // [0,384): sigmoid(gates row A); [384,768): row B; +8 pad for the
    // provably-unused i0+1 overread at the last ns2 group.
    __shared__ float sg[776];

    int row = blockIdx.x;
    int tid = threadIdx.x;
    int c   = tid << 2;

    const float* __restrict__ iA = in + (size_t)row * IN_W;
    const float* __restrict__ iB = iA + (size_t)rowsHalf * IN_W;
    float* __restrict__ oA = out + (size_t)row * OUT_W + c;
    float* __restrict__ oB = oA + (size_t)rowsHalf * OUT_W;

    // Region-dependent input offset (warp-uniform branch).
    int off;
    if (c < 256)       off = c;                   // scalars
    else if (c < 1024) off = 640  + (c - 256);    // ns1 data
    else               off = 1408 + (c - 1024);   // ns2 data

    // Issue the streaming data loads first; their latency overlaps the
    // whole gate phase below.
    float4 a = *reinterpret_cast<const float4*>(iA + off);
    float4 b = *reinterpret_cast<const float4*>(iB + off);

    // Fused gate fill + sigmoid: 2 rows x 96 float4 = 192 threads,
    // each LDG.128 -> 4 sigmoids -> STS.128. One barrier total.
    if (tid < 192) {
        bool rB = tid >= 96;
        int  t  = rB ? tid - 96 : tid;
        const float* gp = (rB ? iB : iA) + 256 + (t << 2);
        float4 g = *reinterpret_cast<const float4*>(gp);
        g.x = sigmoidf_(g.x);
        g.y = sigmoidf_(g.y);
        g.z = sigmoidf_(g.z);
        g.w = sigmoidf_(g.w);
        *reinterpret_cast<float4*>(&sg[(rB ? 384 : 0) + (t << 2)]) = g;
    }
    __syncthreads();

    if (c < 256) {
        // scalars: relu
        a.x = fmaxf(a.x, 0.0f); a.y = fmaxf(a.y, 0.0f);
        a.z = fmaxf(a.z, 0.0f); a.w = fmaxf(a.w, 0.0f);
        b.x = fmaxf(b.x, 0.0f); b.y = fmaxf(b.y, 0.0f);
        b.z = fmaxf(b.z, 0.0f); b.w = fmaxf(b.w, 0.0f);
    } else if (c < 1024) {
        // ns1: 256 groups of 3; gate i0=j/3, i0+1 (<=2 distinct per float4)
        int j  = c - 256;
        int i0 = j / 3;
        int r  = j - 3 * i0;
        float sa0 = sg[i0],       sa1 = sg[i0 + 1];
        float sb0 = sg[384 + i0], sb1 = sg[384 + i0 + 1];
        // lane gate idx: x->i0; y->i0+(r==2); z->i0+(r>=1); w->i0+1
        a.x *= sa0;                      b.x *= sb0;
        a.y *= (r == 2) ? sa1 : sa0;     b.y *= (r == 2) ? sb1 : sb0;
        a.z *= (r >= 1) ? sa1 : sa0;     b.z *= (r >= 1) ? sb1 : sb0;
        a.w *= sa1;                      b.w *= sb1;
    } else {
        // ns2: 128 groups of 5; gates live at sg[256+i] (A), sg[640+i] (B)
        int j  = c - 1024;
        int i0 = j / 5;
        int r  = j - 5 * i0;
        float sa0 = sg[256 + i0], sa1 = sg[256 + i0 + 1]; // i0=127 -> sg[384], unused (r<2)
        float sb0 = sg[640 + i0], sb1 = sg[640 + i0 + 1]; // i0=127 -> sg[768] pad, unused
        // lane gate idx: x->i0; y->i0+(r==4); z->i0+(r>=3); w->i0+(r>=2)
        a.x *= sa0;                      b.x *= sb0;
        a.y *= (r == 4) ? sa1 : sa0;     b.y *= (r == 4) ? sb1 : sb0;
        a.z *= (r >= 3) ? sa1 : sa0;     b.z *= (r >= 3) ? sb1 : sb0;
        a.w *= (r >= 2) ? sa1 : sa0;     b.w *= (r >= 2) ? sb1 : sb0;
    }

    *reinterpret_cast<float4*>(oA) = a;
    *reinterpret_cast<float4*>(oB) = b;
}

extern "C" void kernel_launch(void* const* d_in, const int* in_sizes, int n_in,
                              void* d_out, int out_size) {
    const float* in = (const float*)d_in[0];
    float* out = (float*)d_out;

    int n_rows   = in_sizes[0] / IN_W;      // 65536 (even)
    int rowsHalf = n_rows / 2;

    gbp_kernel<<<rowsHalf, OUT_W4>>>(in, out, rowsHalf);
}